// round 15
// baseline (speedup 1.0000x reference)
#include <cuda_runtime.h>
#include <cuda_fp16.h>
#include <cuda.h>
#include <cstdint>

// Problem constants
#define MROWS 32768            // 8 * 4096 tokens
#define EMBED 1024
#define NQKV  3072             // q|k|v concatenated along N
#define HDIM  64

// GEMM tiling: CTA tile 128x256, BK=32 (SW64), 4-stage TMA pipeline,
// 2 CTAs/SM, TMEM 256 cols.
#define BK 32
#define A_BYTES 8192           // 128 rows x 32 cols fp16 (64 B rows)
#define B_BYTES 16384          // 256 rows x 32 cols fp16
#define STAGE_BYTES (A_BYTES + B_BYTES)   // 24576
#define NSTAGES 4
#define KTILES (EMBED / BK)    // 32

// smem layout (dynamic): [0] tmem ptr, [8..40) full mbars, [40..72) free mbars,
// [72..80) final, [256..512) theta, [1024 ..) stage buffers
#define SM_TMEM  0
#define SM_FULL  8
#define SM_FREE  40
#define SM_MBARF 72
#define SM_THETA 256
#define SM_STG   1024
#define SMEM_TOTAL (SM_STG + NSTAGES * STAGE_BYTES)   // 99328 -> 2 CTAs/SM

// tcgen05 available only in arch-specific (sm_103a / sm_100a) compile passes.
#if defined(__CUDA_ARCH_FEAT_SM103_ALL) || defined(__CUDA_ARCH_FEAT_SM100_ALL) \
    || (defined(__CUDA_ARCH_SPECIFIC__))
#define USE_TCGEN05 1
#else
#define USE_TCGEN05 0
#endif

// idesc kind::f16: dtype=F32(1<<4), a/b FP16(0), N=256 -> 32<<17, M=128 -> 8<<24
#define IDESC_F16_128x256 0x8400010u

// ---------------------------------------------------------------------------
// Scratch (device globals; no runtime allocation allowed)
// ---------------------------------------------------------------------------
__device__ __half g_xh  [(size_t)MROWS * EMBED];   // x in fp16           (64 MB)
__device__ __half g_wcat[(size_t)NQKV  * EMBED];   // [Wq;Wk;Wv] fp16     ( 6 MB)
__device__ __half g_woh [(size_t)EMBED * EMBED];   // Wo fp16             ( 2 MB)
__device__ __half g_qkv [(size_t)MROWS * NQKV];    // cos(proj+theta)     (192 MB)
__device__ __half g_ao  [(size_t)MROWS * EMBED];   // attention output    (64 MB)

// ---------------------------------------------------------------------------
// Common PTX helpers
// ---------------------------------------------------------------------------
__device__ __forceinline__ void ldm4(uint32_t& r0, uint32_t& r1, uint32_t& r2,
                                     uint32_t& r3, uint32_t addr) {
    asm volatile("ldmatrix.sync.aligned.m8n8.x4.shared.b16 {%0,%1,%2,%3}, [%4];\n"
                 : "=r"(r0), "=r"(r1), "=r"(r2), "=r"(r3) : "r"(addr));
}

__device__ __forceinline__ void ldm4t(uint32_t& r0, uint32_t& r1, uint32_t& r2,
                                      uint32_t& r3, uint32_t addr) {
    asm volatile("ldmatrix.sync.aligned.m8n8.x4.trans.shared.b16 {%0,%1,%2,%3}, [%4];\n"
                 : "=r"(r0), "=r"(r1), "=r"(r2), "=r"(r3) : "r"(addr));
}

__device__ __forceinline__ void mma16816(float* c, const uint32_t* a,
                                         const uint32_t* b) {
    asm volatile(
        "mma.sync.aligned.m16n8k16.row.col.f32.f16.f16.f32 "
        "{%0,%1,%2,%3}, {%4,%5,%6,%7}, {%8,%9}, {%0,%1,%2,%3};\n"
        : "+f"(c[0]), "+f"(c[1]), "+f"(c[2]), "+f"(c[3])
        : "r"(a[0]), "r"(a[1]), "r"(a[2]), "r"(a[3]), "r"(b[0]), "r"(b[1]));
}

__device__ __forceinline__ uint32_t elect_one_pred() {
    uint32_t pred;
    asm volatile("{\n\t.reg .pred p;\n\telect.sync _|p, 0xFFFFFFFF;\n\t"
                 "selp.b32 %0, 1, 0, p;\n\t}" : "=r"(pred));
    return pred;
}

#define MBARRIER_INIT(mbar, cnt) \
    asm volatile("mbarrier.init.shared.b64 [%0], %1;" \
                 :: "r"((uint32_t)(mbar)), "r"((uint32_t)(cnt)) : "memory")
#define MBARRIER_INVAL(mbar) \
    asm volatile("mbarrier.inval.shared.b64 [%0];" :: "r"((uint32_t)(mbar)) : "memory")
#define MBARRIER_EXPECT_TX(mbar, bytes) \
    asm volatile("mbarrier.arrive.expect_tx.shared.b64 _, [%0], %1;" \
                 :: "r"((uint32_t)(mbar)), "r"((uint32_t)(bytes)) : "memory")

#define MBARRIER_WAIT_PARITY(mbar, parity) do {                                   \
    uint32_t _m = (uint32_t)(mbar), _p = (uint32_t)(parity), _done;               \
    asm volatile("{\n\t.reg .pred p;\n\t"                                         \
        "mbarrier.try_wait.parity.acquire.cta.shared::cta.b64 p, [%1], %2;\n\t"   \
        "selp.b32 %0, 1, 0, p;\n\t}" : "=r"(_done) : "r"(_m), "r"(_p) : "memory");\
    if (!_done) {                                                                 \
        asm volatile("{\n\t.reg .pred P1;\n\t"                                    \
            "WL_%=:\n\t"                                                          \
            "mbarrier.try_wait.parity.acquire.cta.shared::cta.b64 P1, [%0], %1, 0x989680;\n\t" \
            "@P1 bra.uni WD_%=;\n\t"                                              \
            "bra.uni WL_%=;\n\t"                                                  \
            "WD_%=:\n\t}" :: "r"(_m), "r"(_p) : "memory");                        \
    }                                                                             \
} while (0)

// 2D TMA load global->shared(cta), completion via mbarrier complete_tx
#define TMA_LOAD_2D(saddr, tmap_ptr, cx, cy, mbar) \
    asm volatile("cp.async.bulk.tensor.2d.shared::cta.global.tile.mbarrier::complete_tx::bytes " \
                 "[%0], [%1, {%2, %3}], [%4];" \
                 :: "r"((uint32_t)(saddr)), "l"(tmap_ptr), \
                    "r"((int)(cx)), "r"((int)(cy)), "r"((uint32_t)(mbar)) : "memory")

#if USE_TCGEN05
#define TCGEN05_ALLOC(smem_addr, nCols) \
    asm volatile("tcgen05.alloc.cta_group::1.sync.aligned.shared::cta.b32 [%0], %1;" \
                 :: "r"((uint32_t)(smem_addr)), "r"((uint32_t)(nCols)) : "memory")
#define TCGEN05_DEALLOC(tmem_addr, nCols) \
    asm volatile("tcgen05.dealloc.cta_group::1.sync.aligned.b32 %0, %1;" \
                 :: "r"(tmem_addr), "r"((uint32_t)(nCols)))
#define TCGEN05_RELINQUISH() \
    asm volatile("tcgen05.relinquish_alloc_permit.cta_group::1.sync.aligned;")
#define TCGEN05_COMMIT(mbar) \
    asm volatile("tcgen05.commit.cta_group::1.mbarrier::arrive::one.shared::cluster.b64 [%0];" \
                 :: "r"((uint32_t)(mbar)) : "memory")
#define TCGEN05_FENCE_AFTER() \
    asm volatile("tcgen05.fence::after_thread_sync;" ::: "memory")
#define TCGEN05_WAIT_LD() \
    asm volatile("tcgen05.wait::ld.sync.aligned;" ::: "memory")

// 64-bit SW64 K-major smem descriptor (Blackwell): LBO=1, SBO=32, layout=4.
// SW64 atom = 8 rows x 64 bytes; pairs with CU_TENSOR_MAP_SWIZZLE_64B.
static constexpr uint64_t SMEM_DESC_BASE_SW64 =
    (uint64_t(4) << 61) | (uint64_t(1) << 46) | (uint64_t(32) << 32) |
    (uint64_t(1) << 16);
#define MAKE_SMEM_DESC_SW64(base_addr) \
    (SMEM_DESC_BASE_SW64 | ((uint64_t)((base_addr) >> 4) & 0x3FFF))

// SS-mode f16 MMA (A desc, B desc, D in TMEM, fp32 accum)
__device__ __forceinline__ void mma_f16_ss(uint32_t d_tmem, uint64_t a_desc,
                                           uint64_t b_desc, uint32_t idesc,
                                           uint32_t en) {
    asm volatile("{\n\t.reg .pred p;\n\tsetp.ne.u32 p, %4, 0;\n\t"
                 "tcgen05.mma.cta_group::1.kind::f16 [%0], %1, %2, %3, p;\n\t}"
                 :: "r"(d_tmem), "l"(a_desc), "l"(b_desc), "r"(idesc), "r"(en)
                 : "memory");
}

#define TCGEN05_LD_X32(r, tmem_addr) \
    asm volatile("tcgen05.ld.sync.aligned.32x32b.x32.b32 " \
        "{%0, %1, %2, %3, %4, %5, %6, %7, " \
        " %8, %9, %10, %11, %12, %13, %14, %15, " \
        " %16, %17, %18, %19, %20, %21, %22, %23, " \
        " %24, %25, %26, %27, %28, %29, %30, %31}, [%32];" \
        : "=r"((r)[0]),  "=r"((r)[1]),  "=r"((r)[2]),  "=r"((r)[3]), \
          "=r"((r)[4]),  "=r"((r)[5]),  "=r"((r)[6]),  "=r"((r)[7]), \
          "=r"((r)[8]),  "=r"((r)[9]),  "=r"((r)[10]), "=r"((r)[11]), \
          "=r"((r)[12]), "=r"((r)[13]), "=r"((r)[14]), "=r"((r)[15]), \
          "=r"((r)[16]), "=r"((r)[17]), "=r"((r)[18]), "=r"((r)[19]), \
          "=r"((r)[20]), "=r"((r)[21]), "=r"((r)[22]), "=r"((r)[23]), \
          "=r"((r)[24]), "=r"((r)[25]), "=r"((r)[26]), "=r"((r)[27]), \
          "=r"((r)[28]), "=r"((r)[29]), "=r"((r)[30]), "=r"((r)[31]) \
        : "r"(tmem_addr))
#endif  // USE_TCGEN05

// ---------------------------------------------------------------------------
// Merged fp32 -> fp16 conversion: x, Wq, Wk, Wv, Wo in ONE launch (MLP-4).
// ---------------------------------------------------------------------------
#define F2H_XB ((MROWS * EMBED) / 4096)          // 8192 blocks for x
#define F2H_WB ((EMBED * EMBED) / 4096)          // 256 blocks per weight
#define F2H_BLOCKS (F2H_XB + 4 * F2H_WB)         // 9216

__global__ void __launch_bounds__(256)
f2h_all(const float* __restrict__ x,  const float* __restrict__ Wq,
        const float* __restrict__ Wk, const float* __restrict__ Wv,
        const float* __restrict__ Wo,
        __half* __restrict__ xh, __half* __restrict__ wcat,
        __half* __restrict__ woh) {
    const float* src;
    __half* dst;
    int bid = blockIdx.x;
    if (bid < F2H_XB) {
        src = x; dst = xh;
    } else {
        int r = (bid - F2H_XB) / F2H_WB;
        bid   = bid - F2H_XB - r * F2H_WB;
        switch (r) {
            case 0:  src = Wq; dst = wcat;                     break;
            case 1:  src = Wk; dst = wcat + 1024 * 1024;       break;
            case 2:  src = Wv; dst = wcat + 2 * 1024 * 1024;   break;
            default: src = Wo; dst = woh;                      break;
        }
    }
    const size_t base4 = (size_t)bid * 1024 + threadIdx.x;
    float4 v[4];
#pragma unroll
    for (int k = 0; k < 4; k++)
        v[k] = reinterpret_cast<const float4*>(src)[base4 + k * 256];
#pragma unroll
    for (int k = 0; k < 4; k++) {
        __half2 h[2];
        h[0] = __floats2half2_rn(v[k].x, v[k].y);
        h[1] = __floats2half2_rn(v[k].z, v[k].w);
        reinterpret_cast<uint2*>(dst)[base4 + k * 256] =
            *reinterpret_cast<uint2*>(h);
    }
}

// ---------------------------------------------------------------------------
// NT GEMM: C[M,N] = A[M,K] * B[N,K]^T, fp16 in, fp32 accum.
// CTA tile 128 rows x 256 cols, BK=32 (SW64), 4-stage TMA pipeline,
// single-warp mainloop, 2 CTAs/SM, TMEM 256 cols.
// EPI==0: C half, __cosf(acc+theta[col%64]).  EPI==1: C float.
// ---------------------------------------------------------------------------
template <int EPI>
__global__ void __launch_bounds__(256)
gemm_tc(const __grid_constant__ CUtensorMap tma,
        const __grid_constant__ CUtensorMap tmb,
        const __half* __restrict__ A, const __half* __restrict__ Bm,
        void* __restrict__ Cv, const float* __restrict__ theta, int N) {
    extern __shared__ __align__(1024) char smem_raw[];
    uint32_t smem = (uint32_t)__cvta_generic_to_shared(smem_raw);

    const int tid = threadIdx.x;
    const int lane = tid & 31, wid = tid >> 5;

#if USE_TCGEN05
    // ======================= TMA + tcgen05 + TMEM path =====================
    if (tid == 0) {
#pragma unroll
        for (int s = 0; s < NSTAGES; s++) {
            MBARRIER_INIT(smem + SM_FULL + 8 * s, 1);
            MBARRIER_INIT(smem + SM_FREE + 8 * s, 1);
        }
        MBARRIER_INIT(smem + SM_MBARF, 1);
        asm volatile("fence.proxy.async.shared::cta;" ::: "memory");
    }
    if (wid == 0) {
        TCGEN05_ALLOC(smem + SM_TMEM, 256);
        TCGEN05_RELINQUISH();
    }
    if (EPI == 0 && tid < 64)
        reinterpret_cast<float*>(smem_raw + SM_THETA)[tid] = theta[tid];
    __syncthreads();

    uint32_t tmem;
    asm volatile("ld.shared.b32 %0, [%1];" : "=r"(tmem) : "r"(smem + SM_TMEM));

    const int rowA = blockIdx.y * 128;
    const int rowB = blockIdx.x * 256;

    if (wid == 0 && elect_one_pred()) {
        // prologue: fill all four stages
#pragma unroll
        for (int s = 0; s < NSTAGES; s++) {
            uint32_t stg = smem + SM_STG + s * STAGE_BYTES;
            MBARRIER_EXPECT_TX(smem + SM_FULL + 8 * s, STAGE_BYTES);
            TMA_LOAD_2D(stg,           &tma, s * BK, rowA, smem + SM_FULL + 8 * s);
            TMA_LOAD_2D(stg + A_BYTES, &tmb, s * BK, rowB, smem + SM_FULL + 8 * s);
        }
        // single-warp mainloop: no block barriers
#pragma unroll 1
        for (int kt = 0; kt < KTILES; kt++) {
            const int s = kt % NSTAGES;
            uint32_t stg = smem + SM_STG + s * STAGE_BYTES;
            MBARRIER_WAIT_PARITY(smem + SM_FULL + 8 * s, (kt / NSTAGES) & 1);
            uint64_t ad = MAKE_SMEM_DESC_SW64(stg);
            uint64_t bd = MAKE_SMEM_DESC_SW64(stg + A_BYTES);
#pragma unroll
            for (int ks = 0; ks < 2; ks++)
                mma_f16_ss(tmem, ad + ks * 2, bd + ks * 2,
                           IDESC_F16_128x256, (kt > 0 || ks > 0) ? 1u : 0u);
            TCGEN05_COMMIT(smem + SM_FREE + 8 * s);
            const int kt2 = kt + NSTAGES;
            if (kt2 < KTILES) {
                MBARRIER_WAIT_PARITY(smem + SM_FREE + 8 * s,
                                     ((kt2 / NSTAGES) - 1) & 1);
                MBARRIER_EXPECT_TX(smem + SM_FULL + 8 * s, STAGE_BYTES);
                TMA_LOAD_2D(stg,           &tma, kt2 * BK, rowA,
                            smem + SM_FULL + 8 * s);
                TMA_LOAD_2D(stg + A_BYTES, &tmb, kt2 * BK, rowB,
                            smem + SM_FULL + 8 * s);
            }
        }
        TCGEN05_COMMIT(smem + SM_MBARF);
    }

    // all threads wait for the final MMA, then run the epilogue
    MBARRIER_WAIT_PARITY(smem + SM_MBARF, 0);
    TCGEN05_FENCE_AFTER();

    // epilogue: 128 rows x 256 TMEM cols.
    // warp w: rows (w&3)*32+lane, cols (w>>2)*128 + q*32, q = 0..3
    const int sub = wid & 3;
    const int ch  = wid >> 2;
    const int grow = blockIdx.y * 128 + sub * 32 + lane;
    const int gcol = blockIdx.x * 256 + ch * 128;

#pragma unroll
    for (int q = 0; q < 4; q++) {
        uint32_t d[32];
        TCGEN05_LD_X32(d, tmem + ch * 128 + q * 32);
        TCGEN05_WAIT_LD();
        if (EPI == 0) {
            const float* th = reinterpret_cast<const float*>(smem_raw + SM_THETA);
            const int tb = (q & 1) * 32;   // theta base: cols mod 64
            __half* C = (__half*)Cv + (size_t)grow * N + gcol + q * 32;
#pragma unroll
            for (int g = 0; g < 4; g++) {
                __half2 h[4];
#pragma unroll
                for (int e = 0; e < 4; e++) {
                    int c = g * 8 + e * 2;
                    h[e] = __floats2half2_rn(
                        __cosf(__uint_as_float(d[c])     + th[tb + c]),
                        __cosf(__uint_as_float(d[c + 1]) + th[tb + c + 1]));
                }
                *reinterpret_cast<uint4*>(C + g * 8) =
                    *reinterpret_cast<uint4*>(h);
            }
        } else {
            float* C = (float*)Cv + (size_t)grow * N + gcol + q * 32;
#pragma unroll
            for (int g = 0; g < 8; g++)
                *reinterpret_cast<uint4*>(C + g * 4) =
                    *reinterpret_cast<uint4*>(&d[g * 4]);
        }
    }

    __syncthreads();
    if (tid == 0) {
#pragma unroll
        for (int s = 0; s < NSTAGES; s++) {
            MBARRIER_INVAL(smem + SM_FULL + 8 * s);
            MBARRIER_INVAL(smem + SM_FREE + 8 * s);
        }
        MBARRIER_INVAL(smem + SM_MBARF);
    }
    if (wid == 0) TCGEN05_DEALLOC(tmem, 256);

#else
    // ====== naive fallback (compile-only; arch-specific path always runs) ==
    (void)smem; (void)lane; (void)wid; (void)tma; (void)tmb;
    const int row = blockIdx.y * 128 + (tid >> 1);
    const int colbase = blockIdx.x * 256 + (tid & 1) * 128;
    for (int c = 0; c < 128; c++) {
        float acc = 0.f;
        for (int k = 0; k < EMBED; k++)
            acc += __half2float(A[(size_t)row * EMBED + k]) *
                   __half2float(Bm[(size_t)(colbase + c) * EMBED + k]);
        if (EPI == 0) {
            int col = colbase + c;
            ((__half*)Cv)[(size_t)row * N + col] =
                __float2half(__cosf(acc + theta[col & 63]));
        } else {
            ((float*)Cv)[(size_t)row * N + colbase + c] = acc;
        }
    }
#endif
}

// ---------------------------------------------------------------------------
// Per-token attention over HEADS axis via mma.sync (HMMA).
// One warp per token: scores = q k^T (16x16x64, 8 mmas), softmax in the
// m16n8 accumulator layout (4-lane shfl groups), P repacked fp16 directly
// into the A-fragment layout, out = P v (16x64x16, 8 mmas).
// ---------------------------------------------------------------------------
__global__ void __launch_bounds__(128)
attn_kernel(const __half* __restrict__ qkv, __half* __restrict__ ao) {
    __shared__ __align__(16) __half sq[4][16][72];
    __shared__ __align__(16) __half sk[4][16][72];
    __shared__ __align__(16) __half sv[4][16][72];

    const int w = threadIdx.x >> 5, lane = threadIdx.x & 31;
    const size_t t = (size_t)blockIdx.x * 4 + w;
    const __half* base = qkv + t * 3072;

#pragma unroll
    for (int idx = lane; idx < 128; idx += 32) {
        int row = idx >> 3, c = idx & 7;
        *reinterpret_cast<uint4*>(&sq[w][row][c * 8]) =
            reinterpret_cast<const uint4*>(base)[idx];
        *reinterpret_cast<uint4*>(&sk[w][row][c * 8]) =
            reinterpret_cast<const uint4*>(base + 1024)[idx];
        *reinterpret_cast<uint4*>(&sv[w][row][c * 8]) =
            reinterpret_cast<const uint4*>(base + 2048)[idx];
    }
    __syncwarp();

    const int lrow = lane & 7;
    const int lsel = lane >> 3;   // 0..3
    uint32_t qaddr = (uint32_t)__cvta_generic_to_shared(
        &sq[w][(lsel & 1) * 8 + lrow][(lane >> 4) * 8]);
    uint32_t kaddr = (uint32_t)__cvta_generic_to_shared(
        &sk[w][(lsel >> 1) * 8 + lrow][(lsel & 1) * 8]);
    uint32_t vaddr = (uint32_t)__cvta_generic_to_shared(
        &sv[w][(lsel & 1) * 8 + lrow][(lane >> 4) * 8]);

    // -- scores: two m16n8 accumulators over K=64 (4 chunks) --
    float sc0[4] = {0.f, 0.f, 0.f, 0.f};
    float sc1[4] = {0.f, 0.f, 0.f, 0.f};
#pragma unroll
    for (int kc = 0; kc < 4; kc++) {
        uint32_t a[4], b[4];
        ldm4(a[0], a[1], a[2], a[3], qaddr + kc * 32);
        ldm4(b[0], b[1], b[2], b[3], kaddr + kc * 32);
        uint32_t b0[2] = { b[0], b[1] };
        uint32_t b1[2] = { b[2], b[3] };
        mma16816(sc0, a, b0);
        mma16816(sc1, a, b1);
    }

#pragma unroll
    for (int i = 0; i < 4; i++) { sc0[i] *= 0.125f; sc1[i] *= 0.125f; }
    float mA = fmaxf(fmaxf(sc0[0], sc0[1]), fmaxf(sc1[0], sc1[1]));
    float mB = fmaxf(fmaxf(sc0[2], sc0[3]), fmaxf(sc1[2], sc1[3]));
    mA = fmaxf(mA, __shfl_xor_sync(0xffffffffu, mA, 1));
    mA = fmaxf(mA, __shfl_xor_sync(0xffffffffu, mA, 2));
    mB = fmaxf(mB, __shfl_xor_sync(0xffffffffu, mB, 1));
    mB = fmaxf(mB, __shfl_xor_sync(0xffffffffu, mB, 2));
    float e00 = __expf(sc0[0] - mA), e01 = __expf(sc0[1] - mA);
    float e10 = __expf(sc1[0] - mA), e11 = __expf(sc1[1] - mA);
    float f00 = __expf(sc0[2] - mB), f01 = __expf(sc0[3] - mB);
    float f10 = __expf(sc1[2] - mB), f11 = __expf(sc1[3] - mB);
    float sA = e00 + e01 + e10 + e11;
    float sB = f00 + f01 + f10 + f11;
    sA += __shfl_xor_sync(0xffffffffu, sA, 1);
    sA += __shfl_xor_sync(0xffffffffu, sA, 2);
    sB += __shfl_xor_sync(0xffffffffu, sB, 1);
    sB += __shfl_xor_sync(0xffffffffu, sB, 2);
    float rA = 1.f / sA, rB = 1.f / sB;

    uint32_t pa[4];
    {
        __half2 h;
        h = __floats2half2_rn(e00 * rA, e01 * rA); pa[0] = *(uint32_t*)&h;
        h = __floats2half2_rn(f00 * rB, f01 * rB); pa[1] = *(uint32_t*)&h;
        h = __floats2half2_rn(e10 * rA, e11 * rA); pa[2] = *(uint32_t*)&h;
        h = __floats2half2_rn(f10 * rB, f11 * rB); pa[3] = *(uint32_t*)&h;
    }

    float o[8][4];
#pragma unroll
    for (int nt = 0; nt < 8; nt++)
#pragma unroll
        for (int i = 0; i < 4; i++) o[nt][i] = 0.f;
#pragma unroll
    for (int nc = 0; nc < 4; nc++) {
        uint32_t vb[4];
        ldm4t(vb[0], vb[1], vb[2], vb[3], vaddr + nc * 32);
        uint32_t b0[2] = { vb[0], vb[1] };
        uint32_t b1[2] = { vb[2], vb[3] };
        mma16816(o[nc * 2],     pa, b0);
        mma16816(o[nc * 2 + 1], pa, b1);
    }

    __half* out = ao + t * 1024;
    const int r  = lane >> 2;
    const int j2 = (lane & 3) * 2;
#pragma unroll
    for (int nt = 0; nt < 8; nt++) {
        *reinterpret_cast<__half2*>(out + r * 64 + nt * 8 + j2) =
            __floats2half2_rn(o[nt][0], o[nt][1]);
        *reinterpret_cast<__half2*>(out + (r + 8) * 64 + nt * 8 + j2) =
            __floats2half2_rn(o[nt][2], o[nt][3]);
    }
}

// ---------------------------------------------------------------------------
// Host: tensor map creation via driver entry point (no -lcuda needed)
// ---------------------------------------------------------------------------
typedef CUresult (*PFN_tmapEncode)(
    CUtensorMap*, CUtensorMapDataType, cuuint32_t, void*,
    const cuuint64_t*, const cuuint64_t*, const cuuint32_t*, const cuuint32_t*,
    CUtensorMapInterleave, CUtensorMapSwizzle, CUtensorMapL2promotion,
    CUtensorMapFloatOOBfill);

static void make_tmap_2d(PFN_tmapEncode enc, CUtensorMap* t, void* ptr,
                         unsigned long long rows, unsigned box_rows) {
    cuuint64_t dims[2]    = {EMBED, rows};         // inner = K (contiguous)
    cuuint64_t strides[1] = {EMBED * 2};           // row pitch in bytes
    cuuint32_t box[2]     = {BK, box_rows};        // 32 halves (64 B) x rows
    cuuint32_t es[2]      = {1, 1};
    enc(t, CU_TENSOR_MAP_DATA_TYPE_FLOAT16, 2, ptr, dims, strides, box, es,
        CU_TENSOR_MAP_INTERLEAVE_NONE, CU_TENSOR_MAP_SWIZZLE_64B,
        CU_TENSOR_MAP_L2_PROMOTION_L2_128B, CU_TENSOR_MAP_FLOAT_OOB_FILL_NONE);
}

// ---------------------------------------------------------------------------
// Launch: merged convert -> fused QKV GEMM (+cos epi) -> attention -> Wo GEMM
// Input order per metadata: x, Wk, Wq, Wv, Wo, theta
// ---------------------------------------------------------------------------
extern "C" void kernel_launch(void* const* d_in, const int* in_sizes, int n_in,
                              void* d_out, int out_size) {
    (void)in_sizes; (void)n_in; (void)out_size;
    const float* x  = (const float*)d_in[0];
    const float* Wk = (const float*)d_in[1];
    const float* Wq = (const float*)d_in[2];
    const float* Wv = (const float*)d_in[3];
    const float* Wo = (const float*)d_in[4];
    const float* th = (const float*)d_in[5];

    __half *xh, *wcat, *woh, *qkv, *ao;
    cudaGetSymbolAddress((void**)&xh,   g_xh);
    cudaGetSymbolAddress((void**)&wcat, g_wcat);
    cudaGetSymbolAddress((void**)&woh,  g_woh);
    cudaGetSymbolAddress((void**)&qkv,  g_qkv);
    cudaGetSymbolAddress((void**)&ao,   g_ao);

    // tensor maps (built each call; deterministic)
    PFN_tmapEncode enc = nullptr;
    cudaDriverEntryPointQueryResult qr;
    cudaGetDriverEntryPoint("cuTensorMapEncodeTiled", (void**)&enc,
                            cudaEnableDefault, &qr);
    CUtensorMap tm_x, tm_wcat, tm_ao, tm_wo;
    make_tmap_2d(enc, &tm_x,    xh,   MROWS, 128);   // A of gemm1
    make_tmap_2d(enc, &tm_wcat, wcat, NQKV,  256);   // B of gemm1
    make_tmap_2d(enc, &tm_ao,   ao,   MROWS, 128);   // A of gemm2
    make_tmap_2d(enc, &tm_wo,   woh,  EMBED, 256);   // B of gemm2

    cudaFuncSetAttribute(gemm_tc<0>, cudaFuncAttributeMaxDynamicSharedMemorySize,
                         SMEM_TOTAL);
    cudaFuncSetAttribute(gemm_tc<1>, cudaFuncAttributeMaxDynamicSharedMemorySize,
                         SMEM_TOTAL);

    // merged fp32 -> fp16 (x + all four weights), ONE launch
    f2h_all<<<F2H_BLOCKS, 256>>>(x, Wq, Wk, Wv, Wo, xh, wcat, woh);

    // fused QKV projection + cos(.+theta) epilogue -> g_qkv (half)
    gemm_tc<0><<<dim3(NQKV / 256, MROWS / 128), 256, SMEM_TOTAL>>>(
        tm_x, tm_wcat, xh, wcat, qkv, th, NQKV);

    // per-token 16x16 attention over heads (HMMA)
    attn_kernel<<<MROWS / 4, 128>>>(qkv, ao);

    // output projection -> fp32 d_out
    gemm_tc<1><<<dim3(EMBED / 256, MROWS / 128), 256, SMEM_TOTAL>>>(
        tm_ao, tm_wo, ao, woh, (float*)d_out, nullptr, EMBED);
}

// round 16
// speedup vs baseline: 1.0720x; 1.0720x over previous
#include <cuda_runtime.h>
#include <cuda_fp16.h>
#include <cuda.h>
#include <cstdint>

// Problem constants
#define MROWS 32768            // 8 * 4096 tokens
#define EMBED 1024
#define NQKV  3072             // q|k|v concatenated along N
#define HDIM  64

// GEMM tiling: CTA tile 128x256, BK=64, 2-stage TMA pipeline (2 CTAs/SM)
#define BK 64
#define A_BYTES 16384          // 128 rows x 64 cols fp16
#define B_BYTES 32768          // 256 rows x 64 cols fp16
#define STAGE_BYTES (A_BYTES + B_BYTES)   // 49152
#define NSTAGES 2
#define KTILES (EMBED / BK)    // 16

// smem layout (dynamic): [0] tmem ptr, [8..24) full mbars, [24..40) free mbars,
// [40..48) final, [256..512) theta, [1024 ..) stage buffers
#define SM_TMEM  0
#define SM_FULL  8
#define SM_FREE  24
#define SM_MBARF 40
#define SM_THETA 256
#define SM_STG   1024
#define SMEM_TOTAL (SM_STG + NSTAGES * STAGE_BYTES)   // 99328 -> 2 CTAs/SM

// tcgen05 available only in arch-specific (sm_103a / sm_100a) compile passes.
#if defined(__CUDA_ARCH_FEAT_SM103_ALL) || defined(__CUDA_ARCH_FEAT_SM100_ALL) \
    || (defined(__CUDA_ARCH_SPECIFIC__))
#define USE_TCGEN05 1
#else
#define USE_TCGEN05 0
#endif

// idesc kind::f16: dtype=F32(1<<4), a/b FP16(0), N=256 -> 32<<17, M=128 -> 8<<24
#define IDESC_F16_128x256 0x8400010u

// ---------------------------------------------------------------------------
// Scratch (device globals; no runtime allocation allowed)
// ---------------------------------------------------------------------------
__device__ __half g_xh  [(size_t)MROWS * EMBED];   // x in fp16           (64 MB)
__device__ __half g_wcat[(size_t)NQKV  * EMBED];   // [Wq;Wk;Wv] fp16     ( 6 MB)
__device__ __half g_woh [(size_t)EMBED * EMBED];   // Wo fp16             ( 2 MB)
__device__ __half g_qkv [(size_t)MROWS * NQKV];    // cos(proj+theta)     (192 MB)
__device__ __half g_ao  [(size_t)MROWS * EMBED];   // attention output    (64 MB)

// ---------------------------------------------------------------------------
// Common PTX helpers
// ---------------------------------------------------------------------------
__device__ __forceinline__ void cp16(uint32_t saddr, const void* g) {
    asm volatile("cp.async.cg.shared.global [%0], [%1], 16;\n"
                 :: "r"(saddr), "l"(g));
}

__device__ __forceinline__ void ldm4(uint32_t& r0, uint32_t& r1, uint32_t& r2,
                                     uint32_t& r3, uint32_t addr) {
    asm volatile("ldmatrix.sync.aligned.m8n8.x4.shared.b16 {%0,%1,%2,%3}, [%4];\n"
                 : "=r"(r0), "=r"(r1), "=r"(r2), "=r"(r3) : "r"(addr));
}

__device__ __forceinline__ void ldm4t(uint32_t& r0, uint32_t& r1, uint32_t& r2,
                                      uint32_t& r3, uint32_t addr) {
    asm volatile("ldmatrix.sync.aligned.m8n8.x4.trans.shared.b16 {%0,%1,%2,%3}, [%4];\n"
                 : "=r"(r0), "=r"(r1), "=r"(r2), "=r"(r3) : "r"(addr));
}

__device__ __forceinline__ void mma16816(float* c, const uint32_t* a,
                                         const uint32_t* b) {
    asm volatile(
        "mma.sync.aligned.m16n8k16.row.col.f32.f16.f16.f32 "
        "{%0,%1,%2,%3}, {%4,%5,%6,%7}, {%8,%9}, {%0,%1,%2,%3};\n"
        : "+f"(c[0]), "+f"(c[1]), "+f"(c[2]), "+f"(c[3])
        : "r"(a[0]), "r"(a[1]), "r"(a[2]), "r"(a[3]), "r"(b[0]), "r"(b[1]));
}

__device__ __forceinline__ uint32_t elect_one_pred() {
    uint32_t pred;
    asm volatile("{\n\t.reg .pred p;\n\telect.sync _|p, 0xFFFFFFFF;\n\t"
                 "selp.b32 %0, 1, 0, p;\n\t}" : "=r"(pred));
    return pred;
}

#define MBARRIER_INIT(mbar, cnt) \
    asm volatile("mbarrier.init.shared.b64 [%0], %1;" \
                 :: "r"((uint32_t)(mbar)), "r"((uint32_t)(cnt)) : "memory")
#define MBARRIER_INVAL(mbar) \
    asm volatile("mbarrier.inval.shared.b64 [%0];" :: "r"((uint32_t)(mbar)) : "memory")
#define MBARRIER_EXPECT_TX(mbar, bytes) \
    asm volatile("mbarrier.arrive.expect_tx.shared.b64 _, [%0], %1;" \
                 :: "r"((uint32_t)(mbar)), "r"((uint32_t)(bytes)) : "memory")

#define MBARRIER_WAIT_PARITY(mbar, parity) do {                                   \
    uint32_t _m = (uint32_t)(mbar), _p = (uint32_t)(parity), _done;               \
    asm volatile("{\n\t.reg .pred p;\n\t"                                         \
        "mbarrier.try_wait.parity.acquire.cta.shared::cta.b64 p, [%1], %2;\n\t"   \
        "selp.b32 %0, 1, 0, p;\n\t}" : "=r"(_done) : "r"(_m), "r"(_p) : "memory");\
    if (!_done) {                                                                 \
        asm volatile("{\n\t.reg .pred P1;\n\t"                                    \
            "WL_%=:\n\t"                                                          \
            "mbarrier.try_wait.parity.acquire.cta.shared::cta.b64 P1, [%0], %1, 0x989680;\n\t" \
            "@P1 bra.uni WD_%=;\n\t"                                              \
            "bra.uni WL_%=;\n\t"                                                  \
            "WD_%=:\n\t}" :: "r"(_m), "r"(_p) : "memory");                        \
    }                                                                             \
} while (0)

// 2D TMA load global->shared(cta), completion via mbarrier complete_tx
#define TMA_LOAD_2D(saddr, tmap_ptr, cx, cy, mbar) \
    asm volatile("cp.async.bulk.tensor.2d.shared::cta.global.tile.mbarrier::complete_tx::bytes " \
                 "[%0], [%1, {%2, %3}], [%4];" \
                 :: "r"((uint32_t)(saddr)), "l"(tmap_ptr), \
                    "r"((int)(cx)), "r"((int)(cy)), "r"((uint32_t)(mbar)) : "memory")

#if USE_TCGEN05
#define TCGEN05_ALLOC(smem_addr, nCols) \
    asm volatile("tcgen05.alloc.cta_group::1.sync.aligned.shared::cta.b32 [%0], %1;" \
                 :: "r"((uint32_t)(smem_addr)), "r"((uint32_t)(nCols)) : "memory")
#define TCGEN05_DEALLOC(tmem_addr, nCols) \
    asm volatile("tcgen05.dealloc.cta_group::1.sync.aligned.b32 %0, %1;" \
                 :: "r"(tmem_addr), "r"((uint32_t)(nCols)))
#define TCGEN05_RELINQUISH() \
    asm volatile("tcgen05.relinquish_alloc_permit.cta_group::1.sync.aligned;")
#define TCGEN05_COMMIT(mbar) \
    asm volatile("tcgen05.commit.cta_group::1.mbarrier::arrive::one.shared::cluster.b64 [%0];" \
                 :: "r"((uint32_t)(mbar)) : "memory")
#define TCGEN05_FENCE_AFTER() \
    asm volatile("tcgen05.fence::after_thread_sync;" ::: "memory")
#define TCGEN05_WAIT_LD() \
    asm volatile("tcgen05.wait::ld.sync.aligned;" ::: "memory")

// 64-bit SW128 K-major smem descriptor (Blackwell): LBO=1, SBO=64, layout=2
static constexpr uint64_t SMEM_DESC_BASE_SW128 =
    (uint64_t(2) << 61) | (uint64_t(1) << 46) | (uint64_t(64) << 32) |
    (uint64_t(1) << 16);
#define MAKE_SMEM_DESC(base_addr) \
    (SMEM_DESC_BASE_SW128 | ((uint64_t)((base_addr) >> 4) & 0x3FFF))

// SS-mode f16 MMA (A desc, B desc, D in TMEM, fp32 accum)
__device__ __forceinline__ void mma_f16_ss(uint32_t d_tmem, uint64_t a_desc,
                                           uint64_t b_desc, uint32_t idesc,
                                           uint32_t en) {
    asm volatile("{\n\t.reg .pred p;\n\tsetp.ne.u32 p, %4, 0;\n\t"
                 "tcgen05.mma.cta_group::1.kind::f16 [%0], %1, %2, %3, p;\n\t}"
                 :: "r"(d_tmem), "l"(a_desc), "l"(b_desc), "r"(idesc), "r"(en)
                 : "memory");
}

#define TCGEN05_LD_X32(r, tmem_addr) \
    asm volatile("tcgen05.ld.sync.aligned.32x32b.x32.b32 " \
        "{%0, %1, %2, %3, %4, %5, %6, %7, " \
        " %8, %9, %10, %11, %12, %13, %14, %15, " \
        " %16, %17, %18, %19, %20, %21, %22, %23, " \
        " %24, %25, %26, %27, %28, %29, %30, %31}, [%32];" \
        : "=r"((r)[0]),  "=r"((r)[1]),  "=r"((r)[2]),  "=r"((r)[3]), \
          "=r"((r)[4]),  "=r"((r)[5]),  "=r"((r)[6]),  "=r"((r)[7]), \
          "=r"((r)[8]),  "=r"((r)[9]),  "=r"((r)[10]), "=r"((r)[11]), \
          "=r"((r)[12]), "=r"((r)[13]), "=r"((r)[14]), "=r"((r)[15]), \
          "=r"((r)[16]), "=r"((r)[17]), "=r"((r)[18]), "=r"((r)[19]), \
          "=r"((r)[20]), "=r"((r)[21]), "=r"((r)[22]), "=r"((r)[23]), \
          "=r"((r)[24]), "=r"((r)[25]), "=r"((r)[26]), "=r"((r)[27]), \
          "=r"((r)[28]), "=r"((r)[29]), "=r"((r)[30]), "=r"((r)[31]) \
        : "r"(tmem_addr))
#endif  // USE_TCGEN05

// ---------------------------------------------------------------------------
// Merged fp32 -> fp16 conversion: x, Wq, Wk, Wv, Wo in ONE launch (MLP-4).
// ---------------------------------------------------------------------------
#define F2H_XB ((MROWS * EMBED) / 4096)          // 8192 blocks for x
#define F2H_WB ((EMBED * EMBED) / 4096)          // 256 blocks per weight
#define F2H_BLOCKS (F2H_XB + 4 * F2H_WB)         // 9216

__global__ void __launch_bounds__(256)
f2h_all(const float* __restrict__ x,  const float* __restrict__ Wq,
        const float* __restrict__ Wk, const float* __restrict__ Wv,
        const float* __restrict__ Wo,
        __half* __restrict__ xh, __half* __restrict__ wcat,
        __half* __restrict__ woh) {
    const float* src;
    __half* dst;
    int bid = blockIdx.x;
    if (bid < F2H_XB) {
        src = x; dst = xh;
    } else {
        int r = (bid - F2H_XB) / F2H_WB;
        bid   = bid - F2H_XB - r * F2H_WB;
        switch (r) {
            case 0:  src = Wq; dst = wcat;                     break;
            case 1:  src = Wk; dst = wcat + 1024 * 1024;       break;
            case 2:  src = Wv; dst = wcat + 2 * 1024 * 1024;   break;
            default: src = Wo; dst = woh;                      break;
        }
    }
    const size_t base4 = (size_t)bid * 1024 + threadIdx.x;
    float4 v[4];
#pragma unroll
    for (int k = 0; k < 4; k++)
        v[k] = reinterpret_cast<const float4*>(src)[base4 + k * 256];
#pragma unroll
    for (int k = 0; k < 4; k++) {
        __half2 h[2];
        h[0] = __floats2half2_rn(v[k].x, v[k].y);
        h[1] = __floats2half2_rn(v[k].z, v[k].w);
        reinterpret_cast<uint2*>(dst)[base4 + k * 256] =
            *reinterpret_cast<uint2*>(h);
    }
}

// ---------------------------------------------------------------------------
// NT GEMM: C[M,N] = A[M,K] * B[N,K]^T, fp16 in, fp32 accum.
// CTA tile 128 rows x 256 cols, 2-stage TMA pipeline, single-warp mainloop,
// 2 CTAs/SM, TMEM 256 cols.  (R14 champion configuration.)
// EPI==0: C half, __cosf(acc+theta[col%64]).  EPI==1: C float.
// ---------------------------------------------------------------------------
template <int EPI>
__global__ void __launch_bounds__(256)
gemm_tc(const __grid_constant__ CUtensorMap tma,
        const __grid_constant__ CUtensorMap tmb,
        const __half* __restrict__ A, const __half* __restrict__ Bm,
        void* __restrict__ Cv, const float* __restrict__ theta, int N) {
    extern __shared__ __align__(1024) char smem_raw[];
    uint32_t smem = (uint32_t)__cvta_generic_to_shared(smem_raw);

    const int tid = threadIdx.x;
    const int lane = tid & 31, wid = tid >> 5;

#if USE_TCGEN05
    // ======================= TMA + tcgen05 + TMEM path =====================
    if (tid == 0) {
#pragma unroll
        for (int s = 0; s < NSTAGES; s++) {
            MBARRIER_INIT(smem + SM_FULL + 8 * s, 1);
            MBARRIER_INIT(smem + SM_FREE + 8 * s, 1);
        }
        MBARRIER_INIT(smem + SM_MBARF, 1);
        asm volatile("fence.proxy.async.shared::cta;" ::: "memory");
    }
    if (wid == 0) {
        TCGEN05_ALLOC(smem + SM_TMEM, 256);
        TCGEN05_RELINQUISH();
    }
    if (EPI == 0 && tid < 64)
        reinterpret_cast<float*>(smem_raw + SM_THETA)[tid] = theta[tid];
    __syncthreads();

    uint32_t tmem;
    asm volatile("ld.shared.b32 %0, [%1];" : "=r"(tmem) : "r"(smem + SM_TMEM));

    const int rowA = blockIdx.y * 128;
    const int rowB = blockIdx.x * 256;

    if (wid == 0 && elect_one_pred()) {
        // prologue: fill both stages
#pragma unroll
        for (int s = 0; s < NSTAGES; s++) {
            uint32_t stg = smem + SM_STG + s * STAGE_BYTES;
            MBARRIER_EXPECT_TX(smem + SM_FULL + 8 * s, STAGE_BYTES);
            TMA_LOAD_2D(stg,           &tma, s * BK, rowA, smem + SM_FULL + 8 * s);
            TMA_LOAD_2D(stg + A_BYTES, &tmb, s * BK, rowB, smem + SM_FULL + 8 * s);
        }
        // single-warp mainloop: no block barriers
#pragma unroll 1
        for (int kt = 0; kt < KTILES; kt++) {
            const int s = kt % NSTAGES;
            uint32_t stg = smem + SM_STG + s * STAGE_BYTES;
            MBARRIER_WAIT_PARITY(smem + SM_FULL + 8 * s, (kt / NSTAGES) & 1);
            uint64_t ad = MAKE_SMEM_DESC(stg);
            uint64_t bd = MAKE_SMEM_DESC(stg + A_BYTES);
#pragma unroll
            for (int ks = 0; ks < 4; ks++)
                mma_f16_ss(tmem, ad + ks * 2, bd + ks * 2,
                           IDESC_F16_128x256, (kt > 0 || ks > 0) ? 1u : 0u);
            TCGEN05_COMMIT(smem + SM_FREE + 8 * s);
            const int kt2 = kt + NSTAGES;
            if (kt2 < KTILES) {
                MBARRIER_WAIT_PARITY(smem + SM_FREE + 8 * s,
                                     ((kt2 / NSTAGES) - 1) & 1);
                MBARRIER_EXPECT_TX(smem + SM_FULL + 8 * s, STAGE_BYTES);
                TMA_LOAD_2D(stg,           &tma, kt2 * BK, rowA,
                            smem + SM_FULL + 8 * s);
                TMA_LOAD_2D(stg + A_BYTES, &tmb, kt2 * BK, rowB,
                            smem + SM_FULL + 8 * s);
            }
        }
        TCGEN05_COMMIT(smem + SM_MBARF);
    }

    // all threads wait for the final MMA, then run the epilogue
    MBARRIER_WAIT_PARITY(smem + SM_MBARF, 0);
    TCGEN05_FENCE_AFTER();

    // epilogue: 128 rows x 256 TMEM cols.
    // warp w: rows (w&3)*32+lane, cols (w>>2)*128 + q*32, q = 0..3
    const int sub = wid & 3;
    const int ch  = wid >> 2;
    const int grow = blockIdx.y * 128 + sub * 32 + lane;
    const int gcol = blockIdx.x * 256 + ch * 128;

#pragma unroll
    for (int q = 0; q < 4; q++) {
        uint32_t d[32];
        TCGEN05_LD_X32(d, tmem + ch * 128 + q * 32);
        TCGEN05_WAIT_LD();
        if (EPI == 0) {
            const float* th = reinterpret_cast<const float*>(smem_raw + SM_THETA);
            const int tb = (q & 1) * 32;   // theta base: cols mod 64
            __half* C = (__half*)Cv + (size_t)grow * N + gcol + q * 32;
#pragma unroll
            for (int g = 0; g < 4; g++) {
                __half2 h[4];
#pragma unroll
                for (int e = 0; e < 4; e++) {
                    int c = g * 8 + e * 2;
                    h[e] = __floats2half2_rn(
                        __cosf(__uint_as_float(d[c])     + th[tb + c]),
                        __cosf(__uint_as_float(d[c + 1]) + th[tb + c + 1]));
                }
                *reinterpret_cast<uint4*>(C + g * 8) =
                    *reinterpret_cast<uint4*>(h);
            }
        } else {
            float* C = (float*)Cv + (size_t)grow * N + gcol + q * 32;
#pragma unroll
            for (int g = 0; g < 8; g++)
                *reinterpret_cast<uint4*>(C + g * 4) =
                    *reinterpret_cast<uint4*>(&d[g * 4]);
        }
    }

    __syncthreads();
    if (tid == 0) {
#pragma unroll
        for (int s = 0; s < NSTAGES; s++) {
            MBARRIER_INVAL(smem + SM_FULL + 8 * s);
            MBARRIER_INVAL(smem + SM_FREE + 8 * s);
        }
        MBARRIER_INVAL(smem + SM_MBARF);
    }
    if (wid == 0) TCGEN05_DEALLOC(tmem, 256);

#else
    // ============ mma.sync fallback (compile-only on base pass) ============
    // 128 rows x 256 cols per CTA, as two 128x128 passes.
    (void)tma; (void)tmb;
    const int lr = tid >> 3, lc = tid & 7;
    uint32_t s0 = (uint32_t)lr * 128u + (uint32_t)lc * 16u;
    s0 ^= (s0 >> 3) & 0x70;

    const int wm = (wid & 1) * 64;
    const int wn = (wid >> 1) * 32;

    uint32_t a_off[4];
#pragma unroll
    for (int mt = 0; mt < 4; mt++) {
        int row = wm + mt * 16 + ((lane >> 3) & 1) * 8 + (lane & 7);
        uint32_t bo = (uint32_t)row * 128u + (uint32_t)(lane >> 4) * 16u;
        a_off[mt] = bo ^ ((bo >> 3) & 0x70);
    }
    uint32_t b_off[2];
    {
        int m = lane >> 3;
#pragma unroll
        for (int ntp = 0; ntp < 2; ntp++) {
            int row = wn + ntp * 16 + (m >> 1) * 8 + (lane & 7);
            uint32_t bo = (uint32_t)row * 128u + (uint32_t)(m & 1) * 16u;
            b_off[ntp] = bo ^ ((bo >> 3) & 0x70);
        }
    }

    const int rowbase = blockIdx.y * 128;

    for (int nh = 0; nh < 2; nh++) {
        if (nh) __syncthreads();
        const int colbase = blockIdx.x * 256 + nh * 128;
        const __half* gA = A  + (size_t)(rowbase + lr) * EMBED + lc * 8;
        const __half* gB = Bm + (size_t)(colbase + lr) * EMBED + lc * 8;

        auto issue = [&](int stage, int kt) {
            uint32_t sa = smem + SM_STG + stage * STAGE_BYTES;
            const __half* pa = gA + kt * BK;
            const __half* pb = gB + kt * BK;
#pragma unroll
            for (int r = 0; r < 4; r++) {
                cp16(sa + s0 + r * 4096u,           pa + (size_t)(32 * r) * EMBED);
                cp16(sa + A_BYTES + s0 + r * 4096u, pb + (size_t)(32 * r) * EMBED);
            }
            asm volatile("cp.async.commit_group;\n");
        };

        float acc[4][4][4];
#pragma unroll
        for (int mt = 0; mt < 4; mt++)
#pragma unroll
            for (int nt = 0; nt < 4; nt++)
#pragma unroll
                for (int i = 0; i < 4; i++) acc[mt][nt][i] = 0.f;

        issue(0, 0);
        issue(1, 1);

        for (int kt = 0; kt < KTILES; kt++) {
            asm volatile("cp.async.wait_group 1;\n" ::: "memory");
            __syncthreads();
            uint32_t sa = smem + SM_STG + (kt % NSTAGES) * STAGE_BYTES;
            uint32_t sb = sa + A_BYTES;
#pragma unroll
            for (int ks = 0; ks < 4; ks++) {
                uint32_t a[4][4], b[2][4];
#pragma unroll
                for (int mt = 0; mt < 4; mt++)
                    ldm4(a[mt][0], a[mt][1], a[mt][2], a[mt][3],
                         sa + (a_off[mt] ^ (ks << 5)));
#pragma unroll
                for (int ntp = 0; ntp < 2; ntp++)
                    ldm4(b[ntp][0], b[ntp][1], b[ntp][2], b[ntp][3],
                         sb + (b_off[ntp] ^ (ks << 5)));
#pragma unroll
                for (int mt = 0; mt < 4; mt++)
#pragma unroll
                    for (int nt = 0; nt < 4; nt++) {
                        uint32_t bb[2] = { b[nt >> 1][(nt & 1) * 2],
                                           b[nt >> 1][(nt & 1) * 2 + 1] };
                        mma16816(acc[mt][nt], a[mt], bb);
                    }
            }
            __syncthreads();
            if (kt + 2 < KTILES) issue((kt + 2) % NSTAGES, kt + 2);
            else asm volatile("cp.async.commit_group;\n");
        }

        const int gm0 = rowbase + wm + (lane >> 2);
        const int gn0 = colbase + wn + (lane & 3) * 2;
        if (EPI == 0) {
            __half* C = (__half*)Cv;
#pragma unroll
            for (int nt = 0; nt < 4; nt++) {
                int col = gn0 + nt * 8;
                float t0 = theta[col & 63];
                float t1 = theta[(col + 1) & 63];
#pragma unroll
                for (int mt = 0; mt < 4; mt++) {
                    int row = gm0 + mt * 16;
                    float* c = acc[mt][nt];
                    *reinterpret_cast<__half2*>(C + (size_t)row * N + col) =
                        __floats2half2_rn(__cosf(c[0] + t0), __cosf(c[1] + t1));
                    *reinterpret_cast<__half2*>(C + (size_t)(row + 8) * N + col) =
                        __floats2half2_rn(__cosf(c[2] + t0), __cosf(c[3] + t1));
                }
            }
        } else {
            float* C = (float*)Cv;
#pragma unroll
            for (int nt = 0; nt < 4; nt++) {
                int col = gn0 + nt * 8;
#pragma unroll
                for (int mt = 0; mt < 4; mt++) {
                    int row = gm0 + mt * 16;
                    float* c = acc[mt][nt];
                    *reinterpret_cast<float2*>(C + (size_t)row * N + col) =
                        make_float2(c[0], c[1]);
                    *reinterpret_cast<float2*>(C + (size_t)(row + 8) * N + col) =
                        make_float2(c[2], c[3]);
                }
            }
        }
    }
#endif
}

// ---------------------------------------------------------------------------
// Per-token attention over HEADS axis via mma.sync (HMMA).
// One warp per token: scores = q k^T (16x16x64, 8 mmas), softmax in the
// m16n8 accumulator layout (4-lane shfl groups), P repacked fp16 directly
// into the A-fragment layout, out = P v (16x64x16, 8 mmas).
// ---------------------------------------------------------------------------
__global__ void __launch_bounds__(128)
attn_kernel(const __half* __restrict__ qkv, __half* __restrict__ ao) {
    __shared__ __align__(16) __half sq[4][16][72];
    __shared__ __align__(16) __half sk[4][16][72];
    __shared__ __align__(16) __half sv[4][16][72];

    const int w = threadIdx.x >> 5, lane = threadIdx.x & 31;
    const size_t t = (size_t)blockIdx.x * 4 + w;
    const __half* base = qkv + t * 3072;

#pragma unroll
    for (int idx = lane; idx < 128; idx += 32) {
        int row = idx >> 3, c = idx & 7;
        *reinterpret_cast<uint4*>(&sq[w][row][c * 8]) =
            reinterpret_cast<const uint4*>(base)[idx];
        *reinterpret_cast<uint4*>(&sk[w][row][c * 8]) =
            reinterpret_cast<const uint4*>(base + 1024)[idx];
        *reinterpret_cast<uint4*>(&sv[w][row][c * 8]) =
            reinterpret_cast<const uint4*>(base + 2048)[idx];
    }
    __syncwarp();

    const int lrow = lane & 7;
    const int lsel = lane >> 3;   // 0..3
    uint32_t qaddr = (uint32_t)__cvta_generic_to_shared(
        &sq[w][(lsel & 1) * 8 + lrow][(lane >> 4) * 8]);
    uint32_t kaddr = (uint32_t)__cvta_generic_to_shared(
        &sk[w][(lsel >> 1) * 8 + lrow][(lsel & 1) * 8]);
    uint32_t vaddr = (uint32_t)__cvta_generic_to_shared(
        &sv[w][(lsel & 1) * 8 + lrow][(lane >> 4) * 8]);

    // -- scores: two m16n8 accumulators over K=64 (4 chunks) --
    float sc0[4] = {0.f, 0.f, 0.f, 0.f};
    float sc1[4] = {0.f, 0.f, 0.f, 0.f};
#pragma unroll
    for (int kc = 0; kc < 4; kc++) {
        uint32_t a[4], b[4];
        ldm4(a[0], a[1], a[2], a[3], qaddr + kc * 32);
        ldm4(b[0], b[1], b[2], b[3], kaddr + kc * 32);
        uint32_t b0[2] = { b[0], b[1] };
        uint32_t b1[2] = { b[2], b[3] };
        mma16816(sc0, a, b0);
        mma16816(sc1, a, b1);
    }

#pragma unroll
    for (int i = 0; i < 4; i++) { sc0[i] *= 0.125f; sc1[i] *= 0.125f; }
    float mA = fmaxf(fmaxf(sc0[0], sc0[1]), fmaxf(sc1[0], sc1[1]));
    float mB = fmaxf(fmaxf(sc0[2], sc0[3]), fmaxf(sc1[2], sc1[3]));
    mA = fmaxf(mA, __shfl_xor_sync(0xffffffffu, mA, 1));
    mA = fmaxf(mA, __shfl_xor_sync(0xffffffffu, mA, 2));
    mB = fmaxf(mB, __shfl_xor_sync(0xffffffffu, mB, 1));
    mB = fmaxf(mB, __shfl_xor_sync(0xffffffffu, mB, 2));
    float e00 = __expf(sc0[0] - mA), e01 = __expf(sc0[1] - mA);
    float e10 = __expf(sc1[0] - mA), e11 = __expf(sc1[1] - mA);
    float f00 = __expf(sc0[2] - mB), f01 = __expf(sc0[3] - mB);
    float f10 = __expf(sc1[2] - mB), f11 = __expf(sc1[3] - mB);
    float sA = e00 + e01 + e10 + e11;
    float sB = f00 + f01 + f10 + f11;
    sA += __shfl_xor_sync(0xffffffffu, sA, 1);
    sA += __shfl_xor_sync(0xffffffffu, sA, 2);
    sB += __shfl_xor_sync(0xffffffffu, sB, 1);
    sB += __shfl_xor_sync(0xffffffffu, sB, 2);
    float rA = 1.f / sA, rB = 1.f / sB;

    uint32_t pa[4];
    {
        __half2 h;
        h = __floats2half2_rn(e00 * rA, e01 * rA); pa[0] = *(uint32_t*)&h;
        h = __floats2half2_rn(f00 * rB, f01 * rB); pa[1] = *(uint32_t*)&h;
        h = __floats2half2_rn(e10 * rA, e11 * rA); pa[2] = *(uint32_t*)&h;
        h = __floats2half2_rn(f10 * rB, f11 * rB); pa[3] = *(uint32_t*)&h;
    }

    float o[8][4];
#pragma unroll
    for (int nt = 0; nt < 8; nt++)
#pragma unroll
        for (int i = 0; i < 4; i++) o[nt][i] = 0.f;
#pragma unroll
    for (int nc = 0; nc < 4; nc++) {
        uint32_t vb[4];
        ldm4t(vb[0], vb[1], vb[2], vb[3], vaddr + nc * 32);
        uint32_t b0[2] = { vb[0], vb[1] };
        uint32_t b1[2] = { vb[2], vb[3] };
        mma16816(o[nc * 2],     pa, b0);
        mma16816(o[nc * 2 + 1], pa, b1);
    }

    __half* out = ao + t * 1024;
    const int r  = lane >> 2;
    const int j2 = (lane & 3) * 2;
#pragma unroll
    for (int nt = 0; nt < 8; nt++) {
        *reinterpret_cast<__half2*>(out + r * 64 + nt * 8 + j2) =
            __floats2half2_rn(o[nt][0], o[nt][1]);
        *reinterpret_cast<__half2*>(out + (r + 8) * 64 + nt * 8 + j2) =
            __floats2half2_rn(o[nt][2], o[nt][3]);
    }
}

// ---------------------------------------------------------------------------
// Host: tensor map creation via driver entry point (no -lcuda needed)
// ---------------------------------------------------------------------------
typedef CUresult (*PFN_tmapEncode)(
    CUtensorMap*, CUtensorMapDataType, cuuint32_t, void*,
    const cuuint64_t*, const cuuint64_t*, const cuuint32_t*, const cuuint32_t*,
    CUtensorMapInterleave, CUtensorMapSwizzle, CUtensorMapL2promotion,
    CUtensorMapFloatOOBfill);

static void make_tmap_2d(PFN_tmapEncode enc, CUtensorMap* t, void* ptr,
                         unsigned long long rows, unsigned box_rows) {
    cuuint64_t dims[2]    = {EMBED, rows};         // inner = K (contiguous)
    cuuint64_t strides[1] = {EMBED * 2};           // row pitch in bytes
    cuuint32_t box[2]     = {BK, box_rows};        // 64 halves x box_rows
    cuuint32_t es[2]      = {1, 1};
    enc(t, CU_TENSOR_MAP_DATA_TYPE_FLOAT16, 2, ptr, dims, strides, box, es,
        CU_TENSOR_MAP_INTERLEAVE_NONE, CU_TENSOR_MAP_SWIZZLE_128B,
        CU_TENSOR_MAP_L2_PROMOTION_L2_128B, CU_TENSOR_MAP_FLOAT_OOB_FILL_NONE);
}

// ---------------------------------------------------------------------------
// Launch: merged convert -> fused QKV GEMM (+cos epi) -> attention -> Wo GEMM
// Input order per metadata: x, Wk, Wq, Wv, Wo, theta
// ---------------------------------------------------------------------------
extern "C" void kernel_launch(void* const* d_in, const int* in_sizes, int n_in,
                              void* d_out, int out_size) {
    (void)in_sizes; (void)n_in; (void)out_size;
    const float* x  = (const float*)d_in[0];
    const float* Wk = (const float*)d_in[1];
    const float* Wq = (const float*)d_in[2];
    const float* Wv = (const float*)d_in[3];
    const float* Wo = (const float*)d_in[4];
    const float* th = (const float*)d_in[5];

    __half *xh, *wcat, *woh, *qkv, *ao;
    cudaGetSymbolAddress((void**)&xh,   g_xh);
    cudaGetSymbolAddress((void**)&wcat, g_wcat);
    cudaGetSymbolAddress((void**)&woh,  g_woh);
    cudaGetSymbolAddress((void**)&qkv,  g_qkv);
    cudaGetSymbolAddress((void**)&ao,   g_ao);

    // tensor maps (built each call; deterministic)
    PFN_tmapEncode enc = nullptr;
    cudaDriverEntryPointQueryResult qr;
    cudaGetDriverEntryPoint("cuTensorMapEncodeTiled", (void**)&enc,
                            cudaEnableDefault, &qr);
    CUtensorMap tm_x, tm_wcat, tm_ao, tm_wo;
    make_tmap_2d(enc, &tm_x,    xh,   MROWS, 128);   // A of gemm1
    make_tmap_2d(enc, &tm_wcat, wcat, NQKV,  256);   // B of gemm1
    make_tmap_2d(enc, &tm_ao,   ao,   MROWS, 128);   // A of gemm2
    make_tmap_2d(enc, &tm_wo,   woh,  EMBED, 256);   // B of gemm2

    cudaFuncSetAttribute(gemm_tc<0>, cudaFuncAttributeMaxDynamicSharedMemorySize,
                         SMEM_TOTAL);
    cudaFuncSetAttribute(gemm_tc<1>, cudaFuncAttributeMaxDynamicSharedMemorySize,
                         SMEM_TOTAL);

    // merged fp32 -> fp16 (x + all four weights), ONE launch
    f2h_all<<<F2H_BLOCKS, 256>>>(x, Wq, Wk, Wv, Wo, xh, wcat, woh);

    // fused QKV projection + cos(.+theta) epilogue -> g_qkv (half)
    gemm_tc<0><<<dim3(NQKV / 256, MROWS / 128), 256, SMEM_TOTAL>>>(
        tm_x, tm_wcat, xh, wcat, qkv, th, NQKV);

    // per-token 16x16 attention over heads (HMMA)
    attn_kernel<<<MROWS / 4, 128>>>(qkv, ao);

    // output projection -> fp32 d_out
    gemm_tc<1><<<dim3(EMBED / 256, MROWS / 128), 256, SMEM_TOTAL>>>(
        tm_ao, tm_wo, ao, woh, (float*)d_out, nullptr, EMBED);
}

// round 17
// speedup vs baseline: 1.1036x; 1.0295x over previous
#include <cuda_runtime.h>
#include <cuda_fp16.h>
#include <cuda.h>
#include <cstdint>

// Problem constants
#define MROWS 32768            // 8 * 4096 tokens
#define EMBED 1024
#define NQKV  3072             // q|k|v concatenated along N
#define HDIM  64

// GEMM tiling: CTA tile 128x256, BK=64, 2-stage TMA pipeline (2 CTAs/SM)
#define BK 64
#define A_BYTES 16384          // 128 rows x 64 cols fp16
#define B_BYTES 32768          // 256 rows x 64 cols fp16
#define STAGE_BYTES (A_BYTES + B_BYTES)   // 49152
#define NSTAGES 2
#define KTILES (EMBED / BK)    // 16

// smem layout (dynamic): [0] tmem ptr, [8..24) full mbars, [24..40) free mbars,
// [40..48) final, [256..512) theta, [1024 ..) stage buffers
#define SM_TMEM  0
#define SM_FULL  8
#define SM_FREE  24
#define SM_MBARF 40
#define SM_THETA 256
#define SM_STG   1024
#define SMEM_TOTAL (SM_STG + NSTAGES * STAGE_BYTES)   // 99328 -> 2 CTAs/SM

// tcgen05 available only in arch-specific (sm_103a / sm_100a) compile passes.
#if defined(__CUDA_ARCH_FEAT_SM103_ALL) || defined(__CUDA_ARCH_FEAT_SM100_ALL) \
    || (defined(__CUDA_ARCH_SPECIFIC__))
#define USE_TCGEN05 1
#else
#define USE_TCGEN05 0
#endif

// idesc kind::f16: dtype=F32(1<<4), a/b FP16(0), N=256 -> 32<<17, M=128 -> 8<<24
#define IDESC_F16_128x256 0x8400010u

// ---------------------------------------------------------------------------
// Scratch (device globals; no runtime allocation allowed)
// ---------------------------------------------------------------------------
__device__ __half g_xh  [(size_t)MROWS * EMBED];   // x in fp16           (64 MB)
__device__ __half g_wcat[(size_t)NQKV  * EMBED];   // [Wq;Wk;Wv] fp16     ( 6 MB)
__device__ __half g_woh [(size_t)EMBED * EMBED];   // Wo fp16             ( 2 MB)
__device__ __half g_qkv [(size_t)MROWS * NQKV];    // cos(proj+theta)     (192 MB)
__device__ __half g_ao  [(size_t)MROWS * EMBED];   // attention output    (64 MB)

// ---------------------------------------------------------------------------
// Common PTX helpers
// ---------------------------------------------------------------------------
__device__ __forceinline__ void cp16(uint32_t saddr, const void* g) {
    asm volatile("cp.async.cg.shared.global [%0], [%1], 16;\n"
                 :: "r"(saddr), "l"(g));
}

__device__ __forceinline__ void ldm4(uint32_t& r0, uint32_t& r1, uint32_t& r2,
                                     uint32_t& r3, uint32_t addr) {
    asm volatile("ldmatrix.sync.aligned.m8n8.x4.shared.b16 {%0,%1,%2,%3}, [%4];\n"
                 : "=r"(r0), "=r"(r1), "=r"(r2), "=r"(r3) : "r"(addr));
}

__device__ __forceinline__ void ldm4t(uint32_t& r0, uint32_t& r1, uint32_t& r2,
                                      uint32_t& r3, uint32_t addr) {
    asm volatile("ldmatrix.sync.aligned.m8n8.x4.trans.shared.b16 {%0,%1,%2,%3}, [%4];\n"
                 : "=r"(r0), "=r"(r1), "=r"(r2), "=r"(r3) : "r"(addr));
}

__device__ __forceinline__ void mma16816(float* c, const uint32_t* a,
                                         const uint32_t* b) {
    asm volatile(
        "mma.sync.aligned.m16n8k16.row.col.f32.f16.f16.f32 "
        "{%0,%1,%2,%3}, {%4,%5,%6,%7}, {%8,%9}, {%0,%1,%2,%3};\n"
        : "+f"(c[0]), "+f"(c[1]), "+f"(c[2]), "+f"(c[3])
        : "r"(a[0]), "r"(a[1]), "r"(a[2]), "r"(a[3]), "r"(b[0]), "r"(b[1]));
}

__device__ __forceinline__ uint32_t elect_one_pred() {
    uint32_t pred;
    asm volatile("{\n\t.reg .pred p;\n\telect.sync _|p, 0xFFFFFFFF;\n\t"
                 "selp.b32 %0, 1, 0, p;\n\t}" : "=r"(pred));
    return pred;
}

#define MBARRIER_INIT(mbar, cnt) \
    asm volatile("mbarrier.init.shared.b64 [%0], %1;" \
                 :: "r"((uint32_t)(mbar)), "r"((uint32_t)(cnt)) : "memory")
#define MBARRIER_INVAL(mbar) \
    asm volatile("mbarrier.inval.shared.b64 [%0];" :: "r"((uint32_t)(mbar)) : "memory")
#define MBARRIER_EXPECT_TX(mbar, bytes) \
    asm volatile("mbarrier.arrive.expect_tx.shared.b64 _, [%0], %1;" \
                 :: "r"((uint32_t)(mbar)), "r"((uint32_t)(bytes)) : "memory")

#define MBARRIER_WAIT_PARITY(mbar, parity) do {                                   \
    uint32_t _m = (uint32_t)(mbar), _p = (uint32_t)(parity), _done;               \
    asm volatile("{\n\t.reg .pred p;\n\t"                                         \
        "mbarrier.try_wait.parity.acquire.cta.shared::cta.b64 p, [%1], %2;\n\t"   \
        "selp.b32 %0, 1, 0, p;\n\t}" : "=r"(_done) : "r"(_m), "r"(_p) : "memory");\
    if (!_done) {                                                                 \
        asm volatile("{\n\t.reg .pred P1;\n\t"                                    \
            "WL_%=:\n\t"                                                          \
            "mbarrier.try_wait.parity.acquire.cta.shared::cta.b64 P1, [%0], %1, 0x989680;\n\t" \
            "@P1 bra.uni WD_%=;\n\t"                                              \
            "bra.uni WL_%=;\n\t"                                                  \
            "WD_%=:\n\t}" :: "r"(_m), "r"(_p) : "memory");                        \
    }                                                                             \
} while (0)

// 2D TMA load global->shared(cta), completion via mbarrier complete_tx
#define TMA_LOAD_2D(saddr, tmap_ptr, cx, cy, mbar) \
    asm volatile("cp.async.bulk.tensor.2d.shared::cta.global.tile.mbarrier::complete_tx::bytes " \
                 "[%0], [%1, {%2, %3}], [%4];" \
                 :: "r"((uint32_t)(saddr)), "l"(tmap_ptr), \
                    "r"((int)(cx)), "r"((int)(cy)), "r"((uint32_t)(mbar)) : "memory")

#if USE_TCGEN05
#define TCGEN05_ALLOC(smem_addr, nCols) \
    asm volatile("tcgen05.alloc.cta_group::1.sync.aligned.shared::cta.b32 [%0], %1;" \
                 :: "r"((uint32_t)(smem_addr)), "r"((uint32_t)(nCols)) : "memory")
#define TCGEN05_DEALLOC(tmem_addr, nCols) \
    asm volatile("tcgen05.dealloc.cta_group::1.sync.aligned.b32 %0, %1;" \
                 :: "r"(tmem_addr), "r"((uint32_t)(nCols)))
#define TCGEN05_RELINQUISH() \
    asm volatile("tcgen05.relinquish_alloc_permit.cta_group::1.sync.aligned;")
#define TCGEN05_COMMIT(mbar) \
    asm volatile("tcgen05.commit.cta_group::1.mbarrier::arrive::one.shared::cluster.b64 [%0];" \
                 :: "r"((uint32_t)(mbar)) : "memory")
#define TCGEN05_FENCE_AFTER() \
    asm volatile("tcgen05.fence::after_thread_sync;" ::: "memory")
#define TCGEN05_WAIT_LD() \
    asm volatile("tcgen05.wait::ld.sync.aligned;" ::: "memory")

// 64-bit SW128 K-major smem descriptor (Blackwell): LBO=1, SBO=64, layout=2
static constexpr uint64_t SMEM_DESC_BASE_SW128 =
    (uint64_t(2) << 61) | (uint64_t(1) << 46) | (uint64_t(64) << 32) |
    (uint64_t(1) << 16);
#define MAKE_SMEM_DESC(base_addr) \
    (SMEM_DESC_BASE_SW128 | ((uint64_t)((base_addr) >> 4) & 0x3FFF))

// SS-mode f16 MMA (A desc, B desc, D in TMEM, fp32 accum)
__device__ __forceinline__ void mma_f16_ss(uint32_t d_tmem, uint64_t a_desc,
                                           uint64_t b_desc, uint32_t idesc,
                                           uint32_t en) {
    asm volatile("{\n\t.reg .pred p;\n\tsetp.ne.u32 p, %4, 0;\n\t"
                 "tcgen05.mma.cta_group::1.kind::f16 [%0], %1, %2, %3, p;\n\t}"
                 :: "r"(d_tmem), "l"(a_desc), "l"(b_desc), "r"(idesc), "r"(en)
                 : "memory");
}

#define TCGEN05_LD_X32(r, tmem_addr) \
    asm volatile("tcgen05.ld.sync.aligned.32x32b.x32.b32 " \
        "{%0, %1, %2, %3, %4, %5, %6, %7, " \
        " %8, %9, %10, %11, %12, %13, %14, %15, " \
        " %16, %17, %18, %19, %20, %21, %22, %23, " \
        " %24, %25, %26, %27, %28, %29, %30, %31}, [%32];" \
        : "=r"((r)[0]),  "=r"((r)[1]),  "=r"((r)[2]),  "=r"((r)[3]), \
          "=r"((r)[4]),  "=r"((r)[5]),  "=r"((r)[6]),  "=r"((r)[7]), \
          "=r"((r)[8]),  "=r"((r)[9]),  "=r"((r)[10]), "=r"((r)[11]), \
          "=r"((r)[12]), "=r"((r)[13]), "=r"((r)[14]), "=r"((r)[15]), \
          "=r"((r)[16]), "=r"((r)[17]), "=r"((r)[18]), "=r"((r)[19]), \
          "=r"((r)[20]), "=r"((r)[21]), "=r"((r)[22]), "=r"((r)[23]), \
          "=r"((r)[24]), "=r"((r)[25]), "=r"((r)[26]), "=r"((r)[27]), \
          "=r"((r)[28]), "=r"((r)[29]), "=r"((r)[30]), "=r"((r)[31]) \
        : "r"(tmem_addr))
#endif  // USE_TCGEN05

// ---------------------------------------------------------------------------
// Merged fp32 -> fp16 conversion: x, Wq, Wk, Wv, Wo in ONE launch (MLP-4).
// ---------------------------------------------------------------------------
#define F2H_XB ((MROWS * EMBED) / 4096)          // 8192 blocks for x
#define F2H_WB ((EMBED * EMBED) / 4096)          // 256 blocks per weight
#define F2H_BLOCKS (F2H_XB + 4 * F2H_WB)         // 9216

__global__ void __launch_bounds__(256)
f2h_all(const float* __restrict__ x,  const float* __restrict__ Wq,
        const float* __restrict__ Wk, const float* __restrict__ Wv,
        const float* __restrict__ Wo,
        __half* __restrict__ xh, __half* __restrict__ wcat,
        __half* __restrict__ woh) {
    const float* src;
    __half* dst;
    int bid = blockIdx.x;
    if (bid < F2H_XB) {
        src = x; dst = xh;
    } else {
        int r = (bid - F2H_XB) / F2H_WB;
        bid   = bid - F2H_XB - r * F2H_WB;
        switch (r) {
            case 0:  src = Wq; dst = wcat;                     break;
            case 1:  src = Wk; dst = wcat + 1024 * 1024;       break;
            case 2:  src = Wv; dst = wcat + 2 * 1024 * 1024;   break;
            default: src = Wo; dst = woh;                      break;
        }
    }
    const size_t base4 = (size_t)bid * 1024 + threadIdx.x;
    float4 v[4];
#pragma unroll
    for (int k = 0; k < 4; k++)
        v[k] = reinterpret_cast<const float4*>(src)[base4 + k * 256];
#pragma unroll
    for (int k = 0; k < 4; k++) {
        __half2 h[2];
        h[0] = __floats2half2_rn(v[k].x, v[k].y);
        h[1] = __floats2half2_rn(v[k].z, v[k].w);
        reinterpret_cast<uint2*>(dst)[base4 + k * 256] =
            *reinterpret_cast<uint2*>(h);
    }
}

// ---------------------------------------------------------------------------
// NT GEMM: C[M,N] = A[M,K] * B[N,K]^T, fp16 in, fp32 accum.
// CTA tile 128 rows x 256 cols, 2-stage TMA pipeline, single-warp mainloop,
// 2 CTAs/SM, TMEM 256 cols.  Epilogue: paired LDTM (issue 2, wait once).
// EPI==0: C half, __cosf(acc+theta[col%64]).  EPI==1: C float.
// ---------------------------------------------------------------------------
template <int EPI>
__global__ void __launch_bounds__(256)
gemm_tc(const __grid_constant__ CUtensorMap tma,
        const __grid_constant__ CUtensorMap tmb,
        const __half* __restrict__ A, const __half* __restrict__ Bm,
        void* __restrict__ Cv, const float* __restrict__ theta, int N) {
    extern __shared__ __align__(1024) char smem_raw[];
    uint32_t smem = (uint32_t)__cvta_generic_to_shared(smem_raw);

    const int tid = threadIdx.x;
    const int lane = tid & 31, wid = tid >> 5;

#if USE_TCGEN05
    // ======================= TMA + tcgen05 + TMEM path =====================
    if (tid == 0) {
#pragma unroll
        for (int s = 0; s < NSTAGES; s++) {
            MBARRIER_INIT(smem + SM_FULL + 8 * s, 1);
            MBARRIER_INIT(smem + SM_FREE + 8 * s, 1);
        }
        MBARRIER_INIT(smem + SM_MBARF, 1);
        asm volatile("fence.proxy.async.shared::cta;" ::: "memory");
    }
    if (wid == 0) {
        TCGEN05_ALLOC(smem + SM_TMEM, 256);
        TCGEN05_RELINQUISH();
    }
    if (EPI == 0 && tid < 64)
        reinterpret_cast<float*>(smem_raw + SM_THETA)[tid] = theta[tid];
    __syncthreads();

    uint32_t tmem;
    asm volatile("ld.shared.b32 %0, [%1];" : "=r"(tmem) : "r"(smem + SM_TMEM));

    const int rowA = blockIdx.y * 128;
    const int rowB = blockIdx.x * 256;

    if (wid == 0 && elect_one_pred()) {
        // prologue: fill both stages
#pragma unroll
        for (int s = 0; s < NSTAGES; s++) {
            uint32_t stg = smem + SM_STG + s * STAGE_BYTES;
            MBARRIER_EXPECT_TX(smem + SM_FULL + 8 * s, STAGE_BYTES);
            TMA_LOAD_2D(stg,           &tma, s * BK, rowA, smem + SM_FULL + 8 * s);
            TMA_LOAD_2D(stg + A_BYTES, &tmb, s * BK, rowB, smem + SM_FULL + 8 * s);
        }
        // single-warp mainloop: no block barriers
#pragma unroll 1
        for (int kt = 0; kt < KTILES; kt++) {
            const int s = kt % NSTAGES;
            uint32_t stg = smem + SM_STG + s * STAGE_BYTES;
            MBARRIER_WAIT_PARITY(smem + SM_FULL + 8 * s, (kt / NSTAGES) & 1);
            uint64_t ad = MAKE_SMEM_DESC(stg);
            uint64_t bd = MAKE_SMEM_DESC(stg + A_BYTES);
#pragma unroll
            for (int ks = 0; ks < 4; ks++)
                mma_f16_ss(tmem, ad + ks * 2, bd + ks * 2,
                           IDESC_F16_128x256, (kt > 0 || ks > 0) ? 1u : 0u);
            TCGEN05_COMMIT(smem + SM_FREE + 8 * s);
            const int kt2 = kt + NSTAGES;
            if (kt2 < KTILES) {
                MBARRIER_WAIT_PARITY(smem + SM_FREE + 8 * s,
                                     ((kt2 / NSTAGES) - 1) & 1);
                MBARRIER_EXPECT_TX(smem + SM_FULL + 8 * s, STAGE_BYTES);
                TMA_LOAD_2D(stg,           &tma, kt2 * BK, rowA,
                            smem + SM_FULL + 8 * s);
                TMA_LOAD_2D(stg + A_BYTES, &tmb, kt2 * BK, rowB,
                            smem + SM_FULL + 8 * s);
            }
        }
        TCGEN05_COMMIT(smem + SM_MBARF);
    }

    // all threads wait for the final MMA, then run the epilogue
    MBARRIER_WAIT_PARITY(smem + SM_MBARF, 0);
    TCGEN05_FENCE_AFTER();

    // epilogue: 128 rows x 256 TMEM cols; paired LDTM to overlap latency.
    // warp w: rows (w&3)*32+lane, cols (w>>2)*128 + qp*64 + {0,32}
    const int sub = wid & 3;
    const int ch  = wid >> 2;
    const int grow = blockIdx.y * 128 + sub * 32 + lane;
    const int gcol = blockIdx.x * 256 + ch * 128;

#pragma unroll
    for (int qp = 0; qp < 2; qp++) {
        uint32_t d0[32], d1[32];
        TCGEN05_LD_X32(d0, tmem + ch * 128 + qp * 64);
        TCGEN05_LD_X32(d1, tmem + ch * 128 + qp * 64 + 32);
        TCGEN05_WAIT_LD();
#pragma unroll
        for (int h2 = 0; h2 < 2; h2++) {
            uint32_t* d = h2 ? d1 : d0;
            const int q = qp * 2 + h2;
            if (EPI == 0) {
                const float* th =
                    reinterpret_cast<const float*>(smem_raw + SM_THETA);
                const int tb = (q & 1) * 32;   // theta base: cols mod 64
                __half* C = (__half*)Cv + (size_t)grow * N + gcol + q * 32;
#pragma unroll
                for (int g = 0; g < 4; g++) {
                    __half2 h[4];
#pragma unroll
                    for (int e = 0; e < 4; e++) {
                        int c = g * 8 + e * 2;
                        h[e] = __floats2half2_rn(
                            __cosf(__uint_as_float(d[c])     + th[tb + c]),
                            __cosf(__uint_as_float(d[c + 1]) + th[tb + c + 1]));
                    }
                    *reinterpret_cast<uint4*>(C + g * 8) =
                        *reinterpret_cast<uint4*>(h);
                }
            } else {
                float* C = (float*)Cv + (size_t)grow * N + gcol + q * 32;
#pragma unroll
                for (int g = 0; g < 8; g++)
                    *reinterpret_cast<uint4*>(C + g * 4) =
                        *reinterpret_cast<uint4*>(&d[g * 4]);
            }
        }
    }

    __syncthreads();
    if (tid == 0) {
#pragma unroll
        for (int s = 0; s < NSTAGES; s++) {
            MBARRIER_INVAL(smem + SM_FULL + 8 * s);
            MBARRIER_INVAL(smem + SM_FREE + 8 * s);
        }
        MBARRIER_INVAL(smem + SM_MBARF);
    }
    if (wid == 0) TCGEN05_DEALLOC(tmem, 256);

#else
    // ============ mma.sync fallback (compile-only on base pass) ============
    // 128 rows x 256 cols per CTA, as two 128x128 passes.
    (void)tma; (void)tmb;
    const int lr = tid >> 3, lc = tid & 7;
    uint32_t s0 = (uint32_t)lr * 128u + (uint32_t)lc * 16u;
    s0 ^= (s0 >> 3) & 0x70;

    const int wm = (wid & 1) * 64;
    const int wn = (wid >> 1) * 32;

    uint32_t a_off[4];
#pragma unroll
    for (int mt = 0; mt < 4; mt++) {
        int row = wm + mt * 16 + ((lane >> 3) & 1) * 8 + (lane & 7);
        uint32_t bo = (uint32_t)row * 128u + (uint32_t)(lane >> 4) * 16u;
        a_off[mt] = bo ^ ((bo >> 3) & 0x70);
    }
    uint32_t b_off[2];
    {
        int m = lane >> 3;
#pragma unroll
        for (int ntp = 0; ntp < 2; ntp++) {
            int row = wn + ntp * 16 + (m >> 1) * 8 + (lane & 7);
            uint32_t bo = (uint32_t)row * 128u + (uint32_t)(m & 1) * 16u;
            b_off[ntp] = bo ^ ((bo >> 3) & 0x70);
        }
    }

    const int rowbase = blockIdx.y * 128;

    for (int nh = 0; nh < 2; nh++) {
        if (nh) __syncthreads();
        const int colbase = blockIdx.x * 256 + nh * 128;
        const __half* gA = A  + (size_t)(rowbase + lr) * EMBED + lc * 8;
        const __half* gB = Bm + (size_t)(colbase + lr) * EMBED + lc * 8;

        auto issue = [&](int stage, int kt) {
            uint32_t sa = smem + SM_STG + stage * STAGE_BYTES;
            const __half* pa = gA + kt * BK;
            const __half* pb = gB + kt * BK;
#pragma unroll
            for (int r = 0; r < 4; r++) {
                cp16(sa + s0 + r * 4096u,           pa + (size_t)(32 * r) * EMBED);
                cp16(sa + A_BYTES + s0 + r * 4096u, pb + (size_t)(32 * r) * EMBED);
            }
            asm volatile("cp.async.commit_group;\n");
        };

        float acc[4][4][4];
#pragma unroll
        for (int mt = 0; mt < 4; mt++)
#pragma unroll
            for (int nt = 0; nt < 4; nt++)
#pragma unroll
                for (int i = 0; i < 4; i++) acc[mt][nt][i] = 0.f;

        issue(0, 0);
        issue(1, 1);

        for (int kt = 0; kt < KTILES; kt++) {
            asm volatile("cp.async.wait_group 1;\n" ::: "memory");
            __syncthreads();
            uint32_t sa = smem + SM_STG + (kt % NSTAGES) * STAGE_BYTES;
            uint32_t sb = sa + A_BYTES;
#pragma unroll
            for (int ks = 0; ks < 4; ks++) {
                uint32_t a[4][4], b[2][4];
#pragma unroll
                for (int mt = 0; mt < 4; mt++)
                    ldm4(a[mt][0], a[mt][1], a[mt][2], a[mt][3],
                         sa + (a_off[mt] ^ (ks << 5)));
#pragma unroll
                for (int ntp = 0; ntp < 2; ntp++)
                    ldm4(b[ntp][0], b[ntp][1], b[ntp][2], b[ntp][3],
                         sb + (b_off[ntp] ^ (ks << 5)));
#pragma unroll
                for (int mt = 0; mt < 4; mt++)
#pragma unroll
                    for (int nt = 0; nt < 4; nt++) {
                        uint32_t bb[2] = { b[nt >> 1][(nt & 1) * 2],
                                           b[nt >> 1][(nt & 1) * 2 + 1] };
                        mma16816(acc[mt][nt], a[mt], bb);
                    }
            }
            __syncthreads();
            if (kt + 2 < KTILES) issue((kt + 2) % NSTAGES, kt + 2);
            else asm volatile("cp.async.commit_group;\n");
        }

        const int gm0 = rowbase + wm + (lane >> 2);
        const int gn0 = colbase + wn + (lane & 3) * 2;
        if (EPI == 0) {
            __half* C = (__half*)Cv;
#pragma unroll
            for (int nt = 0; nt < 4; nt++) {
                int col = gn0 + nt * 8;
                float t0 = theta[col & 63];
                float t1 = theta[(col + 1) & 63];
#pragma unroll
                for (int mt = 0; mt < 4; mt++) {
                    int row = gm0 + mt * 16;
                    float* c = acc[mt][nt];
                    *reinterpret_cast<__half2*>(C + (size_t)row * N + col) =
                        __floats2half2_rn(__cosf(c[0] + t0), __cosf(c[1] + t1));
                    *reinterpret_cast<__half2*>(C + (size_t)(row + 8) * N + col) =
                        __floats2half2_rn(__cosf(c[2] + t0), __cosf(c[3] + t1));
                }
            }
        } else {
            float* C = (float*)Cv;
#pragma unroll
            for (int nt = 0; nt < 4; nt++) {
                int col = gn0 + nt * 8;
#pragma unroll
                for (int mt = 0; mt < 4; mt++) {
                    int row = gm0 + mt * 16;
                    float* c = acc[mt][nt];
                    *reinterpret_cast<float2*>(C + (size_t)row * N + col) =
                        make_float2(c[0], c[1]);
                    *reinterpret_cast<float2*>(C + (size_t)(row + 8) * N + col) =
                        make_float2(c[2], c[3]);
                }
            }
        }
    }
#endif
}

// ---------------------------------------------------------------------------
// Per-token attention over HEADS axis via mma.sync (HMMA).
// One warp per token: scores = q k^T (16x16x64, 8 mmas), softmax in the
// m16n8 accumulator layout (4-lane shfl groups), P repacked fp16 directly
// into the A-fragment layout, out = P v (16x64x16, 8 mmas).
// ---------------------------------------------------------------------------
__global__ void __launch_bounds__(128)
attn_kernel(const __half* __restrict__ qkv, __half* __restrict__ ao) {
    __shared__ __align__(16) __half sq[4][16][72];
    __shared__ __align__(16) __half sk[4][16][72];
    __shared__ __align__(16) __half sv[4][16][72];

    const int w = threadIdx.x >> 5, lane = threadIdx.x & 31;
    const size_t t = (size_t)blockIdx.x * 4 + w;
    const __half* base = qkv + t * 3072;

#pragma unroll
    for (int idx = lane; idx < 128; idx += 32) {
        int row = idx >> 3, c = idx & 7;
        *reinterpret_cast<uint4*>(&sq[w][row][c * 8]) =
            reinterpret_cast<const uint4*>(base)[idx];
        *reinterpret_cast<uint4*>(&sk[w][row][c * 8]) =
            reinterpret_cast<const uint4*>(base + 1024)[idx];
        *reinterpret_cast<uint4*>(&sv[w][row][c * 8]) =
            reinterpret_cast<const uint4*>(base + 2048)[idx];
    }
    __syncwarp();

    const int lrow = lane & 7;
    const int lsel = lane >> 3;   // 0..3
    uint32_t qaddr = (uint32_t)__cvta_generic_to_shared(
        &sq[w][(lsel & 1) * 8 + lrow][(lane >> 4) * 8]);
    uint32_t kaddr = (uint32_t)__cvta_generic_to_shared(
        &sk[w][(lsel >> 1) * 8 + lrow][(lsel & 1) * 8]);
    uint32_t vaddr = (uint32_t)__cvta_generic_to_shared(
        &sv[w][(lsel & 1) * 8 + lrow][(lane >> 4) * 8]);

    // -- scores: two m16n8 accumulators over K=64 (4 chunks) --
    float sc0[4] = {0.f, 0.f, 0.f, 0.f};
    float sc1[4] = {0.f, 0.f, 0.f, 0.f};
#pragma unroll
    for (int kc = 0; kc < 4; kc++) {
        uint32_t a[4], b[4];
        ldm4(a[0], a[1], a[2], a[3], qaddr + kc * 32);
        ldm4(b[0], b[1], b[2], b[3], kaddr + kc * 32);
        uint32_t b0[2] = { b[0], b[1] };
        uint32_t b1[2] = { b[2], b[3] };
        mma16816(sc0, a, b0);
        mma16816(sc1, a, b1);
    }

#pragma unroll
    for (int i = 0; i < 4; i++) { sc0[i] *= 0.125f; sc1[i] *= 0.125f; }
    float mA = fmaxf(fmaxf(sc0[0], sc0[1]), fmaxf(sc1[0], sc1[1]));
    float mB = fmaxf(fmaxf(sc0[2], sc0[3]), fmaxf(sc1[2], sc1[3]));
    mA = fmaxf(mA, __shfl_xor_sync(0xffffffffu, mA, 1));
    mA = fmaxf(mA, __shfl_xor_sync(0xffffffffu, mA, 2));
    mB = fmaxf(mB, __shfl_xor_sync(0xffffffffu, mB, 1));
    mB = fmaxf(mB, __shfl_xor_sync(0xffffffffu, mB, 2));
    float e00 = __expf(sc0[0] - mA), e01 = __expf(sc0[1] - mA);
    float e10 = __expf(sc1[0] - mA), e11 = __expf(sc1[1] - mA);
    float f00 = __expf(sc0[2] - mB), f01 = __expf(sc0[3] - mB);
    float f10 = __expf(sc1[2] - mB), f11 = __expf(sc1[3] - mB);
    float sA = e00 + e01 + e10 + e11;
    float sB = f00 + f01 + f10 + f11;
    sA += __shfl_xor_sync(0xffffffffu, sA, 1);
    sA += __shfl_xor_sync(0xffffffffu, sA, 2);
    sB += __shfl_xor_sync(0xffffffffu, sB, 1);
    sB += __shfl_xor_sync(0xffffffffu, sB, 2);
    float rA = 1.f / sA, rB = 1.f / sB;

    uint32_t pa[4];
    {
        __half2 h;
        h = __floats2half2_rn(e00 * rA, e01 * rA); pa[0] = *(uint32_t*)&h;
        h = __floats2half2_rn(f00 * rB, f01 * rB); pa[1] = *(uint32_t*)&h;
        h = __floats2half2_rn(e10 * rA, e11 * rA); pa[2] = *(uint32_t*)&h;
        h = __floats2half2_rn(f10 * rB, f11 * rB); pa[3] = *(uint32_t*)&h;
    }

    float o[8][4];
#pragma unroll
    for (int nt = 0; nt < 8; nt++)
#pragma unroll
        for (int i = 0; i < 4; i++) o[nt][i] = 0.f;
#pragma unroll
    for (int nc = 0; nc < 4; nc++) {
        uint32_t vb[4];
        ldm4t(vb[0], vb[1], vb[2], vb[3], vaddr + nc * 32);
        uint32_t b0[2] = { vb[0], vb[1] };
        uint32_t b1[2] = { vb[2], vb[3] };
        mma16816(o[nc * 2],     pa, b0);
        mma16816(o[nc * 2 + 1], pa, b1);
    }

    __half* out = ao + t * 1024;
    const int r  = lane >> 2;
    const int j2 = (lane & 3) * 2;
#pragma unroll
    for (int nt = 0; nt < 8; nt++) {
        *reinterpret_cast<__half2*>(out + r * 64 + nt * 8 + j2) =
            __floats2half2_rn(o[nt][0], o[nt][1]);
        *reinterpret_cast<__half2*>(out + (r + 8) * 64 + nt * 8 + j2) =
            __floats2half2_rn(o[nt][2], o[nt][3]);
    }
}

// ---------------------------------------------------------------------------
// Host: tensor map creation via driver entry point (no -lcuda needed)
// ---------------------------------------------------------------------------
typedef CUresult (*PFN_tmapEncode)(
    CUtensorMap*, CUtensorMapDataType, cuuint32_t, void*,
    const cuuint64_t*, const cuuint64_t*, const cuuint32_t*, const cuuint32_t*,
    CUtensorMapInterleave, CUtensorMapSwizzle, CUtensorMapL2promotion,
    CUtensorMapFloatOOBfill);

static void make_tmap_2d(PFN_tmapEncode enc, CUtensorMap* t, void* ptr,
                         unsigned long long rows, unsigned box_rows) {
    cuuint64_t dims[2]    = {EMBED, rows};         // inner = K (contiguous)
    cuuint64_t strides[1] = {EMBED * 2};           // row pitch in bytes
    cuuint32_t box[2]     = {BK, box_rows};        // 64 halves x box_rows
    cuuint32_t es[2]      = {1, 1};
    enc(t, CU_TENSOR_MAP_DATA_TYPE_FLOAT16, 2, ptr, dims, strides, box, es,
        CU_TENSOR_MAP_INTERLEAVE_NONE, CU_TENSOR_MAP_SWIZZLE_128B,
        CU_TENSOR_MAP_L2_PROMOTION_L2_128B, CU_TENSOR_MAP_FLOAT_OOB_FILL_NONE);
}

// ---------------------------------------------------------------------------
// Launch: merged convert -> fused QKV GEMM (+cos epi) -> attention -> Wo GEMM
// Input order per metadata: x, Wk, Wq, Wv, Wo, theta
// ---------------------------------------------------------------------------
extern "C" void kernel_launch(void* const* d_in, const int* in_sizes, int n_in,
                              void* d_out, int out_size) {
    (void)in_sizes; (void)n_in; (void)out_size;
    const float* x  = (const float*)d_in[0];
    const float* Wk = (const float*)d_in[1];
    const float* Wq = (const float*)d_in[2];
    const float* Wv = (const float*)d_in[3];
    const float* Wo = (const float*)d_in[4];
    const float* th = (const float*)d_in[5];

    __half *xh, *wcat, *woh, *qkv, *ao;
    cudaGetSymbolAddress((void**)&xh,   g_xh);
    cudaGetSymbolAddress((void**)&wcat, g_wcat);
    cudaGetSymbolAddress((void**)&woh,  g_woh);
    cudaGetSymbolAddress((void**)&qkv,  g_qkv);
    cudaGetSymbolAddress((void**)&ao,   g_ao);

    // tensor maps (built each call; deterministic)
    PFN_tmapEncode enc = nullptr;
    cudaDriverEntryPointQueryResult qr;
    cudaGetDriverEntryPoint("cuTensorMapEncodeTiled", (void**)&enc,
                            cudaEnableDefault, &qr);
    CUtensorMap tm_x, tm_wcat, tm_ao, tm_wo;
    make_tmap_2d(enc, &tm_x,    xh,   MROWS, 128);   // A of gemm1
    make_tmap_2d(enc, &tm_wcat, wcat, NQKV,  256);   // B of gemm1
    make_tmap_2d(enc, &tm_ao,   ao,   MROWS, 128);   // A of gemm2
    make_tmap_2d(enc, &tm_wo,   woh,  EMBED, 256);   // B of gemm2

    cudaFuncSetAttribute(gemm_tc<0>, cudaFuncAttributeMaxDynamicSharedMemorySize,
                         SMEM_TOTAL);
    cudaFuncSetAttribute(gemm_tc<1>, cudaFuncAttributeMaxDynamicSharedMemorySize,
                         SMEM_TOTAL);

    // merged fp32 -> fp16 (x + all four weights), ONE launch
    f2h_all<<<F2H_BLOCKS, 256>>>(x, Wq, Wk, Wv, Wo, xh, wcat, woh);

    // fused QKV projection + cos(.+theta) epilogue -> g_qkv (half)
    gemm_tc<0><<<dim3(NQKV / 256, MROWS / 128), 256, SMEM_TOTAL>>>(
        tm_x, tm_wcat, xh, wcat, qkv, th, NQKV);

    // per-token 16x16 attention over heads (HMMA)
    attn_kernel<<<MROWS / 4, 128>>>(qkv, ao);

    // output projection -> fp32 d_out
    gemm_tc<1><<<dim3(EMBED / 256, MROWS / 128), 256, SMEM_TOTAL>>>(
        tm_ao, tm_wo, ao, woh, (float*)d_out, nullptr, EMBED);
}